// round 10
// baseline (speedup 1.0000x reference)
#include <cuda_runtime.h>
#include <math.h>

// Problem constants: z_e [32,64,32,32] f32, emb [1024,64] f32
// Output (concatenated f32): z_st [32,64,32,32] (2097152) | loss (1) | perplexity (1) | encodings [32768,1024] (33554432)
#define NPTS   32768
#define DDIM   64
#define KCODES 1024
#define HWSZ   1024          // H*W
#define OFF_LOSS 2097152
#define OFF_PERP 2097153
#define OFF_ENC  2097154     // NOTE: byte offset 8 mod 16 -> encodings region is only 8B-aligned
#define TK 128               // codes per shared tile

__device__ int   g_idx[NPTS];
__device__ float g_losspart[256];

// ---- packed f32x2 helpers: two independent IEEE-rn fp32 FMAs per instruction.
// Bit-identical to two scalar fmaf() calls; doubles fma-pipe work per instr.
__device__ __forceinline__ unsigned long long fma2(unsigned long long a,
                                                   unsigned long long b,
                                                   unsigned long long c) {
    unsigned long long d;
    asm("fma.rn.f32x2 %0, %1, %2, %3;" : "=l"(d) : "l"(a), "l"(b), "l"(c));
    return d;
}
__device__ __forceinline__ unsigned long long splat2(float v) {
    unsigned long long r;
    asm("mov.b64 %0, {%1, %1};" : "=l"(r) : "f"(v));
    return r;
}
__device__ __forceinline__ void unpack2(unsigned long long p, float& lo, float& hi) {
    asm("mov.b64 {%0, %1}, %2;" : "=f"(lo), "=f"(hi) : "l"(p));
}

// Kernel B: fused encodings-zeroing + emb-norms + argmin + z_st + one-hot + loss partials
__global__ void __launch_bounds__(128, 2) vq_main(const float* __restrict__ z_e,
                                                  const float* __restrict__ emb,
                                                  float* __restrict__ out) {
    // d-major transposed tile: sEt[d][code]. Adjacent codes at fixed d are
    // adjacent floats -> one broadcast LDS.128 feeds two f32x2 operand pairs.
    __shared__ float sEt[DDIM][TK];
    __shared__ float sN[TK];
    __shared__ float sRed[4];

    const int tid = threadIdx.x;
    const int n   = blockIdx.x * 128 + tid;
    const int b   = n >> 10;
    const int hw  = n & 1023;

    // Zero this block's 128 one-hot rows (512 KB, coalesced STG.64.CS).
    // Region is only 8B-aligned (OFF_ENC*4 = 8 mod 16): float2 max width.
    // Streaming stores drain behind the FMA mainloop (replaces 134 MB memset).
    {
        float2* encBase = (float2*)(out + (size_t)OFF_ENC)
                        + (size_t)blockIdx.x * (128 * KCODES / 2);
        const float2 z2 = make_float2(0.f, 0.f);
        #pragma unroll 8
        for (int i = 0; i < (128 * KCODES / 2) / 128; i++)
            __stcs(&encBase[tid + i * 128], z2);
    }

    // Load x: z_e[b][d][h][w], coalesced across lanes (hw contiguous)
    const float* xp = z_e + (size_t)b * (DDIM * HWSZ) + hw;
    float x[DDIM];
    #pragma unroll
    for (int d = 0; d < DDIM; d++) x[d] = xp[(size_t)d * HWSZ];

    // nx = ||x||^2, sequential in-order FMA (reference rounding)
    float nx = 0.f;
    #pragma unroll
    for (int d = 0; d < DDIM; d++) nx = fmaf(x[d], x[d], nx);

    // Prescale by -2 (exact power-of-2 scale commutes with rn rounding):
    // accumulated chain == -fl(2*dot) with reference-identical rounding.
    #pragma unroll
    for (int d = 0; d < DDIM; d++) x[d] = -2.f * x[d];

    float best  = __int_as_float(0x7f800000);  // +inf
    int   bestk = 0;

    for (int kt = 0; kt < KCODES; kt += TK) {
        __syncthreads();
        // Stage tile transposed + compute this tile's norms (fused, replaces
        // the old vq_enorm kernel). Thread tid owns code kt+tid; norm is the
        // same sequential in-order d=0..63 FMA chain as before (bit-identical).
        {
            const float4* src = (const float4*)(emb + (size_t)(kt + tid) * DDIM);
            float s = 0.f;
            #pragma unroll
            for (int i = 0; i < DDIM / 4; i++) {
                float4 v = src[i];
                sEt[4 * i + 0][tid] = v.x;   // bank = tid%32 per lane: conflict-free
                sEt[4 * i + 1][tid] = v.y;
                sEt[4 * i + 2][tid] = v.z;
                sEt[4 * i + 3][tid] = v.w;
                s = fmaf(v.x, v.x, s);
                s = fmaf(v.y, v.y, s);
                s = fmaf(v.z, v.z, s);
                s = fmaf(v.w, v.w, s);
            }
            sN[tid] = s;
        }
        __syncthreads();

        #pragma unroll 1
        for (int kk = 0; kk < TK; kk += 8) {
            // rp[d*32] = codes kk..kk+3 at dim d (16B, aligned); +1 = kk+4..kk+7
            const ulonglong2* rp = (const ulonglong2*)&sEt[0][kk];
            unsigned long long a0 = 0ull, a1 = 0ull, a2 = 0ull, a3 = 0ull;
            // 4 packed chains = 8 codes. Each lane of each chain is the same
            // sequential d=0..63 fmaf order as the scalar version: bit-identical.
            #pragma unroll
            for (int d = 0; d < DDIM; d++) {
                unsigned long long xx = splat2(x[d]);
                ulonglong2 q0 = rp[d * (TK / 4)];
                ulonglong2 q1 = rp[d * (TK / 4) + 1];
                a0 = fma2(xx, q0.x, a0);
                a1 = fma2(xx, q0.y, a1);
                a2 = fma2(xx, q1.x, a2);
                a3 = fma2(xx, q1.y, a3);
            }
            float s0, s1, s2, s3, s4, s5, s6, s7;
            unpack2(a0, s0, s1); unpack2(a1, s2, s3);
            unpack2(a2, s4, s5); unpack2(a3, s6, s7);
            // dist = fl( fl(nx + ne_k) + (-2*dot) ) ; strict < keeps first min,
            // scan order ascending in k == reference argmin tie rule.
            float dd;
            dd = (nx + sN[kk + 0]) + s0; if (dd < best) { best = dd; bestk = kt + kk + 0; }
            dd = (nx + sN[kk + 1]) + s1; if (dd < best) { best = dd; bestk = kt + kk + 1; }
            dd = (nx + sN[kk + 2]) + s2; if (dd < best) { best = dd; bestk = kt + kk + 2; }
            dd = (nx + sN[kk + 3]) + s3; if (dd < best) { best = dd; bestk = kt + kk + 3; }
            dd = (nx + sN[kk + 4]) + s4; if (dd < best) { best = dd; bestk = kt + kk + 4; }
            dd = (nx + sN[kk + 5]) + s5; if (dd < best) { best = dd; bestk = kt + kk + 5; }
            dd = (nx + sN[kk + 6]) + s6; if (dd < best) { best = dd; bestk = kt + kk + 6; }
            dd = (nx + sN[kk + 7]) + s7; if (dd < best) { best = dd; bestk = kt + kk + 7; }
        }
    }

    g_idx[n] = bestk;

    // Epilogue: z_st = z + (z_q - z) (bit-exact reference op sequence),
    // loss partial, one-hot scatter. 1.0f store ordered after this block's
    // zero-stores by the tile-loop __syncthreads barriers.
    const float* eq = emb + (size_t)bestk * DDIM;
    float* zst = out + (size_t)b * (DDIM * HWSZ) + hw;
    float lsum = 0.f;
    #pragma unroll
    for (int d = 0; d < DDIM; d++) {
        float z  = -0.5f * x[d];        // exact recovery of original z
        float zq = eq[d];
        float t  = zq - z;
        __stcs(&zst[(size_t)d * HWSZ], z + t);
        lsum = fmaf(t, t, lsum);
    }
    __stcs(out + (size_t)OFF_ENC + (size_t)n * KCODES + bestk, 1.0f);

    // block reduce loss partial
    #pragma unroll
    for (int off = 16; off; off >>= 1)
        lsum += __shfl_down_sync(0xffffffffu, lsum, off);
    if ((tid & 31) == 0) sRed[tid >> 5] = lsum;
    __syncthreads();
    if (tid == 0)
        g_losspart[blockIdx.x] = (sRed[0] + sRed[1]) + (sRed[2] + sRed[3]);
}

// Kernel C: histogram -> perplexity, sum loss partials -> loss
__global__ void __launch_bounds__(1024) vq_final(float* __restrict__ out) {
    __shared__ int   hist[KCODES];
    __shared__ float red[KCODES];
    int t = threadIdx.x;
    hist[t] = 0;
    __syncthreads();
    #pragma unroll
    for (int i = 0; i < NPTS / KCODES; i++)
        atomicAdd(&hist[g_idx[t + i * KCODES]], 1);
    __syncthreads();

    float p = (float)hist[t] * (1.f / 32768.f);   // exact: divide by 2^15
    red[t] = p * logf(p + 1e-10f);
    __syncthreads();
    #pragma unroll
    for (int s = 512; s; s >>= 1) {
        if (t < s) red[t] += red[t + s];
        __syncthreads();
    }
    float S = red[0];
    __syncthreads();

    red[t] = (t < 256) ? g_losspart[t] : 0.f;
    __syncthreads();
    #pragma unroll
    for (int s = 512; s; s >>= 1) {
        if (t < s) red[t] += red[t + s];
        __syncthreads();
    }
    if (t == 0) {
        float m = red[0] * (1.f / 2097152.f);     // exact: divide by 2^21
        out[OFF_LOSS] = m + 0.25f * m;            // q_loss + 0.25*e_loss, same association
        out[OFF_PERP] = expf(-S);
    }
}

extern "C" void kernel_launch(void* const* d_in, const int* in_sizes, int n_in,
                              void* d_out, int out_size) {
    const float* z_e = (const float*)d_in[0];
    const float* emb = (const float*)d_in[1];
    float* out = (float*)d_out;

    vq_main<<<NPTS / 128, 128>>>(z_e, emb, out);
    vq_final<<<1, 1024>>>(out);
    (void)in_sizes; (void)n_in; (void)out_size;
}

// round 11
// speedup vs baseline: 1.6601x; 1.6601x over previous
#include <cuda_runtime.h>
#include <math.h>

// Problem constants: z_e [32,64,32,32] f32, emb [1024,64] f32
// Output (f32): z_st [2097152] | loss | perplexity | encodings [32768,1024]
#define NPTS   32768
#define DDIM   64
#define KCODES 1024
#define HWSZ   1024
#define OFF_LOSS 2097152
#define OFF_PERP 2097153
#define OFF_ENC  2097154     // byte offset 8 mod 16 -> encodings only 8B-aligned
#define TK 128               // codes per CTA (one split)
#define NSPLIT 8             // code-axis splits per point
#define NGRP   128           // point groups of 256

__device__ float g_pd[NSPLIT * NPTS];   // partial best dist per (split, point)
__device__ int   g_pk[NSPLIT * NPTS];   // partial best code  per (split, point)
__device__ int   g_hist[KCODES];
__device__ float g_losspart[256];

// ---- packed f32x2: two independent IEEE-rn fp32 FMAs (bit-identical to 2x fmaf)
__device__ __forceinline__ unsigned long long fma2(unsigned long long a,
                                                   unsigned long long b,
                                                   unsigned long long c) {
    unsigned long long d;
    asm("fma.rn.f32x2 %0, %1, %2, %3;" : "=l"(d) : "l"(a), "l"(b), "l"(c));
    return d;
}
__device__ __forceinline__ unsigned long long splat2(float v) {
    unsigned long long r;
    asm("mov.b64 %0, {%1, %1};" : "=l"(r) : "f"(v));
    return r;
}
__device__ __forceinline__ void unpack2(unsigned long long p, float& lo, float& hi) {
    asm("mov.b64 {%0, %1}, %2;" : "=f"(lo), "=f"(hi) : "l"(p));
}

// Kernel 1: distance partials. Grid = 1024 CTAs x 128 threads.
// CTA (g, s): points g*256 .. g*256+255 (2 per thread) x codes s*128 .. s*128+127.
// Fine-grained quanta fix the ceil(256/148) CTA imbalance (15.6% -> 1.2%);
// 2 points/thread halves broadcast-LDS traffic per FMA.
__global__ void __launch_bounds__(128, 2) vq_main(const float* __restrict__ z_e,
                                                  const float* __restrict__ emb,
                                                  float* __restrict__ out) {
    __shared__ float sEt[DDIM][TK];   // d-major transposed tile
    __shared__ float sN[TK];

    const int tid = threadIdx.x;
    const int bid = blockIdx.x;
    const int s   = bid & (NSPLIT - 1);
    const int g   = bid >> 3;
    const int kt0 = s * TK;

    // Zero 1/1024 of the encodings region (coalesced STG.64.CS; region is
    // only 8B-aligned so float2 is max width). Stream-ordered before the
    // merge kernel's one-hot writes.
    {
        float2* encB = (float2*)(out + (size_t)OFF_ENC) + (size_t)bid * 16384;
        const float2 z2 = make_float2(0.f, 0.f);
        #pragma unroll 8
        for (int i = 0; i < 128; i++)
            __stcs(&encB[tid + i * 128], z2);
    }
    // Zero the histogram once (stream-ordered before merge's atomics).
    if (bid == 0) {
        #pragma unroll
        for (int j = 0; j < KCODES / 128; j++) g_hist[tid + j * 128] = 0;
    }

    // Stage tile transposed + this tile's norms (sequential in-order FMA,
    // reference rounding). Thread tid owns code kt0+tid.
    {
        const float4* src = (const float4*)(emb + (size_t)(kt0 + tid) * DDIM);
        float nsum = 0.f;
        #pragma unroll
        for (int i = 0; i < DDIM / 4; i++) {
            float4 v = src[i];
            sEt[4 * i + 0][tid] = v.x;
            sEt[4 * i + 1][tid] = v.y;
            sEt[4 * i + 2][tid] = v.z;
            sEt[4 * i + 3][tid] = v.w;
            nsum = fmaf(v.x, v.x, nsum);
            nsum = fmaf(v.y, v.y, nsum);
            nsum = fmaf(v.z, v.z, nsum);
            nsum = fmaf(v.w, v.w, nsum);
        }
        sN[tid] = nsum;
    }

    // Two points per thread: pA = g*256+tid, pB = pA+128.
    const int pA = g * 256 + tid;
    const int pB = pA + 128;
    const float* xpA = z_e + (size_t)(pA >> 10) * (DDIM * HWSZ) + (pA & 1023);
    const float* xpB = z_e + (size_t)(pB >> 10) * (DDIM * HWSZ) + (pB & 1023);

    float xA[DDIM], xB[DDIM];
    #pragma unroll
    for (int d = 0; d < DDIM; d++) { xA[d] = xpA[(size_t)d * HWSZ]; xB[d] = xpB[(size_t)d * HWSZ]; }

    float nxA = 0.f, nxB = 0.f;
    #pragma unroll
    for (int d = 0; d < DDIM; d++) { nxA = fmaf(xA[d], xA[d], nxA); nxB = fmaf(xB[d], xB[d], nxB); }

    // Exact -2 prescale: chain accumulates -fl(2*dot) with reference rounding.
    #pragma unroll
    for (int d = 0; d < DDIM; d++) { xA[d] = -2.f * xA[d]; xB[d] = -2.f * xB[d]; }

    __syncthreads();

    float bestA = __int_as_float(0x7f800000), bestB = bestA;
    int   bkA = kt0, bkB = kt0;

    #pragma unroll 1
    for (int kk = 0; kk < TK; kk += 8) {
        const ulonglong2* rp = (const ulonglong2*)&sEt[0][kk];
        unsigned long long aA0 = 0, aA1 = 0, aA2 = 0, aA3 = 0;
        unsigned long long aB0 = 0, aB1 = 0, aB2 = 0, aB3 = 0;
        // Each chain lane = sequential d=0..63 fmaf order: bit-identical to ref.
        // The two LDS.128 per d feed both points (8 FFMA2 : 2 LDS).
        #pragma unroll
        for (int d = 0; d < DDIM; d++) {
            ulonglong2 q0 = rp[d * (TK / 4)];
            ulonglong2 q1 = rp[d * (TK / 4) + 1];
            unsigned long long xa = splat2(xA[d]);
            unsigned long long xb = splat2(xB[d]);
            aA0 = fma2(xa, q0.x, aA0); aA1 = fma2(xa, q0.y, aA1);
            aA2 = fma2(xa, q1.x, aA2); aA3 = fma2(xa, q1.y, aA3);
            aB0 = fma2(xb, q0.x, aB0); aB1 = fma2(xb, q0.y, aB1);
            aB2 = fma2(xb, q1.x, aB2); aB3 = fma2(xb, q1.y, aB3);
        }
        float t0, t1, t2, t3, t4, t5, t6, t7, dd;
        unpack2(aA0, t0, t1); unpack2(aA1, t2, t3); unpack2(aA2, t4, t5); unpack2(aA3, t6, t7);
        // dist = fl( fl(nx+ne) + (-2dot) ); strict < ascending k == ref tie rule
        dd = (nxA + sN[kk + 0]) + t0; if (dd < bestA) { bestA = dd; bkA = kt0 + kk + 0; }
        dd = (nxA + sN[kk + 1]) + t1; if (dd < bestA) { bestA = dd; bkA = kt0 + kk + 1; }
        dd = (nxA + sN[kk + 2]) + t2; if (dd < bestA) { bestA = dd; bkA = kt0 + kk + 2; }
        dd = (nxA + sN[kk + 3]) + t3; if (dd < bestA) { bestA = dd; bkA = kt0 + kk + 3; }
        dd = (nxA + sN[kk + 4]) + t4; if (dd < bestA) { bestA = dd; bkA = kt0 + kk + 4; }
        dd = (nxA + sN[kk + 5]) + t5; if (dd < bestA) { bestA = dd; bkA = kt0 + kk + 5; }
        dd = (nxA + sN[kk + 6]) + t6; if (dd < bestA) { bestA = dd; bkA = kt0 + kk + 6; }
        dd = (nxA + sN[kk + 7]) + t7; if (dd < bestA) { bestA = dd; bkA = kt0 + kk + 7; }
        unpack2(aB0, t0, t1); unpack2(aB1, t2, t3); unpack2(aB2, t4, t5); unpack2(aB3, t6, t7);
        dd = (nxB + sN[kk + 0]) + t0; if (dd < bestB) { bestB = dd; bkB = kt0 + kk + 0; }
        dd = (nxB + sN[kk + 1]) + t1; if (dd < bestB) { bestB = dd; bkB = kt0 + kk + 1; }
        dd = (nxB + sN[kk + 2]) + t2; if (dd < bestB) { bestB = dd; bkB = kt0 + kk + 2; }
        dd = (nxB + sN[kk + 3]) + t3; if (dd < bestB) { bestB = dd; bkB = kt0 + kk + 3; }
        dd = (nxB + sN[kk + 4]) + t4; if (dd < bestB) { bestB = dd; bkB = kt0 + kk + 4; }
        dd = (nxB + sN[kk + 5]) + t5; if (dd < bestB) { bestB = dd; bkB = kt0 + kk + 5; }
        dd = (nxB + sN[kk + 6]) + t6; if (dd < bestB) { bestB = dd; bkB = kt0 + kk + 6; }
        dd = (nxB + sN[kk + 7]) + t7; if (dd < bestB) { bestB = dd; bkB = kt0 + kk + 7; }
    }

    g_pd[s * NPTS + pA] = bestA;  g_pk[s * NPTS + pA] = bkA;
    g_pd[s * NPTS + pB] = bestB;  g_pk[s * NPTS + pB] = bkB;
}

// Kernel 2: merge partials (ascending split == ascending k: exact ref tie rule),
// then epilogue: z_st, one-hot, histogram atomics, loss partials.
__global__ void __launch_bounds__(128) vq_merge(const float* __restrict__ z_e,
                                                const float* __restrict__ emb,
                                                float* __restrict__ out) {
    __shared__ float sRed[4];
    const int tid = threadIdx.x;
    const int n   = blockIdx.x * 128 + tid;
    const int b   = n >> 10;
    const int hw  = n & 1023;

    float best = __int_as_float(0x7f800000);
    int   bk   = 0;
    #pragma unroll
    for (int s = 0; s < NSPLIT; s++) {
        float d = g_pd[s * NPTS + n];
        int   k = g_pk[s * NPTS + n];
        if (d < best) { best = d; bk = k; }
    }
    atomicAdd(&g_hist[bk], 1);

    // Epilogue: bit-exact reference op sequence z + (z_q - z)
    const float* xp = z_e + (size_t)b * (DDIM * HWSZ) + hw;
    const float* eq = emb + (size_t)bk * DDIM;
    float* zst = out + (size_t)b * (DDIM * HWSZ) + hw;
    float lsum = 0.f;
    #pragma unroll
    for (int d = 0; d < DDIM; d++) {
        float z  = xp[(size_t)d * HWSZ];
        float t  = eq[d] - z;
        __stcs(&zst[(size_t)d * HWSZ], z + t);
        lsum = fmaf(t, t, lsum);
    }
    __stcs(out + (size_t)OFF_ENC + (size_t)n * KCODES + bk, 1.0f);

    #pragma unroll
    for (int off = 16; off; off >>= 1)
        lsum += __shfl_down_sync(0xffffffffu, lsum, off);
    if ((tid & 31) == 0) sRed[tid >> 5] = lsum;
    __syncthreads();
    if (tid == 0)
        g_losspart[blockIdx.x] = (sRed[0] + sRed[1]) + (sRed[2] + sRed[3]);
}

// Kernel 3: entropy over histogram + loss partial sum
__global__ void __launch_bounds__(1024) vq_final(float* __restrict__ out) {
    __shared__ float red[KCODES];
    int t = threadIdx.x;

    float p = (float)g_hist[t] * (1.f / 32768.f);   // exact: /2^15
    red[t] = p * logf(p + 1e-10f);
    __syncthreads();
    #pragma unroll
    for (int s = 512; s; s >>= 1) {
        if (t < s) red[t] += red[t + s];
        __syncthreads();
    }
    float S = red[0];
    __syncthreads();

    red[t] = (t < 256) ? g_losspart[t] : 0.f;
    __syncthreads();
    #pragma unroll
    for (int s = 512; s; s >>= 1) {
        if (t < s) red[t] += red[t + s];
        __syncthreads();
    }
    if (t == 0) {
        float m = red[0] * (1.f / 2097152.f);       // exact: /2^21
        out[OFF_LOSS] = m + 0.25f * m;
        out[OFF_PERP] = expf(-S);
    }
}

extern "C" void kernel_launch(void* const* d_in, const int* in_sizes, int n_in,
                              void* d_out, int out_size) {
    const float* z_e = (const float*)d_in[0];
    const float* emb = (const float*)d_in[1];
    float* out = (float*)d_out;

    vq_main <<<NGRP * NSPLIT, 128>>>(z_e, emb, out);
    vq_merge<<<NPTS / 128, 128>>>(z_e, emb, out);
    vq_final<<<1, 1024>>>(out);
    (void)in_sizes; (void)n_in; (void)out_size;
}